// round 3
// baseline (speedup 1.0000x reference)
#include <cuda_runtime.h>
#include <math.h>

#define BB 4
#define TT 4096
#define CC 1024
#define HH 64
#define NROWS (BB*TT)

// Scratch for projected K (=x@Wq), Q (=x@Wk), V (=x@Wv)  [ref swaps q/k names]
__device__ float g_K[NROWS*HH];
__device__ float g_Q[NROWS*HH];
__device__ float g_V[NROWS*HH];

// ---------------------------------------------------------------------------
// QKV projection: C[16384,192] = X[16384,1024] @ [Wq|Wk|Wv]
// Block tile: 64 rows x 192 cols, 256 threads, 4x12 micro-tile, K staged by 32.
// Static smem: 32 KB (under the 48 KB static cap).
// ---------------------------------------------------------------------------
__global__ __launch_bounds__(256) void qkv_kernel(
    const float* __restrict__ x, const float* __restrict__ Wq,
    const float* __restrict__ Wk, const float* __restrict__ Wv)
{
    __shared__ float xs[32][64];    // [k][m] (transposed for broadcast A reads)
    __shared__ float ws[32][192];   // [k][n]
    const int tid = threadIdx.x;
    const int ty = tid >> 4;        // 0..15 -> rows ty*4..ty*4+3
    const int tx = tid & 15;        // 0..15 -> cols tx*12..tx*12+11
    const int m0 = blockIdx.x * 64;

    float acc[4][12];
    #pragma unroll
    for (int i = 0; i < 4; i++)
        #pragma unroll
        for (int j = 0; j < 12; j++) acc[i][j] = 0.f;

    for (int k0 = 0; k0 < CC; k0 += 32) {
        // X tile: 64 rows x 32 k (float4 along k, transpose into xs[k][m])
        #pragma unroll
        for (int l = 0; l < 2; l++) {
            int idx = tid + l * 256;          // 0..511
            int r = idx >> 3, kq = idx & 7;
            float4 v = *(const float4*)&x[(size_t)(m0 + r) * CC + k0 + kq * 4];
            xs[kq*4+0][r] = v.x; xs[kq*4+1][r] = v.y;
            xs[kq*4+2][r] = v.z; xs[kq*4+3][r] = v.w;
        }
        // W tile: 32 k x 192 cols (Wq -> cols 0..63, Wk -> 64..127, Wv -> 128..191)
        #pragma unroll
        for (int l = 0; l < 6; l++) {
            int idx = tid + l * 256;          // 0..1535
            int k = idx / 48, f = idx % 48;
            const float* Wm = (f < 16) ? Wq : (f < 32) ? Wk : Wv;
            int c4 = f & 15;
            float4 v = *(const float4*)&Wm[(size_t)(k0 + k) * HH + c4 * 4];
            *(float4*)&ws[k][(f >> 4) * 64 + c4 * 4] = v;
        }
        __syncthreads();

        #pragma unroll
        for (int k = 0; k < 32; k++) {
            float4 av = *(const float4*)&xs[k][ty * 4];
            float a[4] = {av.x, av.y, av.z, av.w};
            float b[12];
            #pragma unroll
            for (int j4 = 0; j4 < 3; j4++) {
                float4 bv = *(const float4*)&ws[k][tx * 12 + j4 * 4];
                b[j4*4+0] = bv.x; b[j4*4+1] = bv.y;
                b[j4*4+2] = bv.z; b[j4*4+3] = bv.w;
            }
            #pragma unroll
            for (int i = 0; i < 4; i++)
                #pragma unroll
                for (int j = 0; j < 12; j++)
                    acc[i][j] = fmaf(a[i], b[j], acc[i][j]);
        }
        __syncthreads();
    }

    #pragma unroll
    for (int i = 0; i < 4; i++) {
        int row = m0 + ty * 4 + i;
        #pragma unroll
        for (int j = 0; j < 12; j++) {
            int col = tx * 12 + j;
            float* dst = (col < 64) ? g_K : (col < 128) ? g_Q : g_V;
            dst[(size_t)row * HH + (col & 63)] = acc[i][j];
        }
    }
}

// ---------------------------------------------------------------------------
// Flash attention, fp32, BQ = BK = 64, 256 threads (16x16 grid, 4x4 micro).
// DYNAMIC shared memory (68,608 B > 48 KB static cap -> extern + attribute).
// Each block processes the work-balanced q-tile pair (i, 63-i): every block
// does exactly (i+1) + (64-i) = 65 key tiles -> no causal imbalance.
// Online-softmax stats (m,l) live in registers, replicated across the 16
// threads of each row (identical post-shuffle values -> no smem races).
// ---------------------------------------------------------------------------
#define ATTN_SMEM_BYTES ((2*64*68 + 64*64 + 64*68) * 4)   // 68608

__global__ __launch_bounds__(256) void attn_kernel(float* __restrict__ out)
{
    extern __shared__ float smem[];
    float (*Qt)[68] = (float(*)[68])(smem);                        // [h][m]
    float (*Kt)[68] = (float(*)[68])(smem + 64*68);                // [h][n]
    float (*Vs)[64] = (float(*)[64])(smem + 2*64*68);              // [n][h]
    float (*Ps)[68] = (float(*)[68])(smem + 2*64*68 + 64*64);      // [m][n]

    const int tid = threadIdx.x;
    const int ty = tid >> 4;       // row group 0..15
    const int tx = tid & 15;       // col group 0..15
    const int b  = blockIdx.y;
    const float scale = 0.03125f;  // 1024^-0.5

    for (int pass = 0; pass < 2; pass++) {
        const int qt = pass ? (63 - (int)blockIdx.x) : (int)blockIdx.x;
        const int q0 = qt * 64;

        __syncthreads();
        // Load Q tile transposed: Qt[h][r] = g_Q[(b*T + q0 + r)*64 + h]
        #pragma unroll
        for (int l = 0; l < 4; l++) {
            int idx = tid + l * 256;          // 0..1023
            int r = idx >> 4, h4 = idx & 15;
            float4 v = *(const float4*)&g_Q[((size_t)b * TT + q0 + r) * HH + h4 * 4];
            Qt[h4*4+0][r] = v.x; Qt[h4*4+1][r] = v.y;
            Qt[h4*4+2][r] = v.z; Qt[h4*4+3][r] = v.w;
        }
        __syncthreads();

        float o[4][4];
        float m_i[4], l_i[4];
        #pragma unroll
        for (int i = 0; i < 4; i++) {
            m_i[i] = -INFINITY; l_i[i] = 0.f;
            #pragma unroll
            for (int j = 0; j < 4; j++) o[i][j] = 0.f;
        }

        for (int kt = 0; kt <= qt; kt++) {
            const int k0 = kt * 64;
            __syncthreads();   // prior iteration's PV compute done with Kt/Vs/Ps
            // Load K tile (transposed) + V tile
            #pragma unroll
            for (int l = 0; l < 4; l++) {
                int idx = tid + l * 256;
                int r = idx >> 4, h4 = idx & 15;
                size_t base = ((size_t)b * TT + k0 + r) * HH + h4 * 4;
                float4 kv = *(const float4*)&g_K[base];
                Kt[h4*4+0][r] = kv.x; Kt[h4*4+1][r] = kv.y;
                Kt[h4*4+2][r] = kv.z; Kt[h4*4+3][r] = kv.w;
                *(float4*)&Vs[r][h4 * 4] = *(const float4*)&g_V[base];
            }
            __syncthreads();

            // S = Q K^T  (4x4 per thread)
            float s[4][4];
            #pragma unroll
            for (int i = 0; i < 4; i++)
                #pragma unroll
                for (int j = 0; j < 4; j++) s[i][j] = 0.f;

            #pragma unroll 8
            for (int h = 0; h < 64; h++) {
                float4 a4 = *(const float4*)&Qt[h][ty * 4];
                float4 b4 = *(const float4*)&Kt[h][tx * 4];
                float a[4] = {a4.x, a4.y, a4.z, a4.w};
                float bb[4] = {b4.x, b4.y, b4.z, b4.w};
                #pragma unroll
                for (int i = 0; i < 4; i++)
                    #pragma unroll
                    for (int j = 0; j < 4; j++)
                        s[i][j] = fmaf(a[i], bb[j], s[i][j]);
            }

            // scale + causal mask (only diagonal tile needs masking)
            if (kt == qt) {
                #pragma unroll
                for (int i = 0; i < 4; i++)
                    #pragma unroll
                    for (int j = 0; j < 4; j++) {
                        int qi = ty * 4 + i, kj = tx * 4 + j;
                        s[i][j] = (kj <= qi) ? s[i][j] * scale : -INFINITY;
                    }
            } else {
                #pragma unroll
                for (int i = 0; i < 4; i++)
                    #pragma unroll
                    for (int j = 0; j < 4; j++) s[i][j] *= scale;
            }

            // Online softmax update (row reductions across the 16 tx lanes)
            #pragma unroll
            for (int i = 0; i < 4; i++) {
                float mt = fmaxf(fmaxf(s[i][0], s[i][1]), fmaxf(s[i][2], s[i][3]));
                mt = fmaxf(mt, __shfl_xor_sync(0xffffffffu, mt, 8));
                mt = fmaxf(mt, __shfl_xor_sync(0xffffffffu, mt, 4));
                mt = fmaxf(mt, __shfl_xor_sync(0xffffffffu, mt, 2));
                mt = fmaxf(mt, __shfl_xor_sync(0xffffffffu, mt, 1));
                float m_new = fmaxf(m_i[i], mt);
                float alpha = __expf(m_i[i] - m_new);
                float lt = 0.f;
                #pragma unroll
                for (int j = 0; j < 4; j++) {
                    s[i][j] = __expf(s[i][j] - m_new);
                    lt += s[i][j];
                }
                lt += __shfl_xor_sync(0xffffffffu, lt, 8);
                lt += __shfl_xor_sync(0xffffffffu, lt, 4);
                lt += __shfl_xor_sync(0xffffffffu, lt, 2);
                lt += __shfl_xor_sync(0xffffffffu, lt, 1);
                l_i[i] = l_i[i] * alpha + lt;
                m_i[i] = m_new;
                #pragma unroll
                for (int j = 0; j < 4; j++) o[i][j] *= alpha;
            }

            // Stage P tile
            #pragma unroll
            for (int i = 0; i < 4; i++)
                *(float4*)&Ps[ty * 4 + i][tx * 4] =
                    make_float4(s[i][0], s[i][1], s[i][2], s[i][3]);
            __syncthreads();

            // O += P @ V
            #pragma unroll 8
            for (int j = 0; j < 64; j++) {
                float4 v4 = *(const float4*)&Vs[j][tx * 4];
                float vv[4] = {v4.x, v4.y, v4.z, v4.w};
                #pragma unroll
                for (int i = 0; i < 4; i++) {
                    float p = Ps[ty * 4 + i][j];
                    o[i][0] = fmaf(p, vv[0], o[i][0]);
                    o[i][1] = fmaf(p, vv[1], o[i][1]);
                    o[i][2] = fmaf(p, vv[2], o[i][2]);
                    o[i][3] = fmaf(p, vv[3], o[i][3]);
                }
            }
        }

        // Epilogue: normalize and write
        #pragma unroll
        for (int i = 0; i < 4; i++) {
            float inv = 1.f / l_i[i];
            float4 r4 = make_float4(o[i][0] * inv, o[i][1] * inv,
                                    o[i][2] * inv, o[i][3] * inv);
            *(float4*)&out[((size_t)b * TT + q0 + ty * 4 + i) * HH + tx * 4] = r4;
        }
    }
}

extern "C" void kernel_launch(void* const* d_in, const int* in_sizes, int n_in,
                              void* d_out, int out_size) {
    const float* x  = (const float*)d_in[0];
    const float* Wq = (const float*)d_in[1];
    const float* Wk = (const float*)d_in[2];
    const float* Wv = (const float*)d_in[3];
    float* out = (float*)d_out;

    // Opt-in to >48KB dynamic shared memory for the attention kernel.
    // (Function-attribute set: not an allocation, not a stream op -> graph-safe.)
    cudaFuncSetAttribute(attn_kernel,
                         cudaFuncAttributeMaxDynamicSharedMemorySize,
                         ATTN_SMEM_BYTES);

    qkv_kernel<<<NROWS / 64, 256>>>(x, Wq, Wk, Wv);
    attn_kernel<<<dim3(32, BB), 256, ATTN_SMEM_BYTES>>>(out);
}

// round 17
// speedup vs baseline: 2.7921x; 2.7921x over previous
#include <cuda_runtime.h>
#include <math.h>
#include <stdint.h>

#define BB 4
#define TT 4096
#define CC 1024
#define HH 64
#define NROWS (BB*TT)

// Scratch for projected K (=x@Wq), Q (=x@Wk, pre-scaled by C^-0.5), V (=x@Wv)
// All stored tf32-rounded (low mantissa bits zero) for the attention mma path.
__device__ float g_K[NROWS*HH];
__device__ float g_Q[NROWS*HH];
__device__ float g_V[NROWS*HH];

__device__ __forceinline__ void mma_tf32(float* d, const uint32_t* a,
                                         uint32_t b0, uint32_t b1) {
    asm volatile(
        "mma.sync.aligned.m16n8k8.row.col.f32.tf32.tf32.f32 "
        "{%0,%1,%2,%3}, {%4,%5,%6,%7}, {%8,%9}, {%0,%1,%2,%3};\n"
        : "+f"(d[0]), "+f"(d[1]), "+f"(d[2]), "+f"(d[3])
        : "r"(a[0]), "r"(a[1]), "r"(a[2]), "r"(a[3]), "r"(b0), "r"(b1));
}

__device__ __forceinline__ float to_tf32(float v) {
    uint32_t u;
    asm("cvt.rna.tf32.f32 %0, %1;" : "=r"(u) : "f"(v));
    return __uint_as_float(u);
}

// ---------------------------------------------------------------------------
// QKV projection via tf32 mma: C[16384,192] = X[16384,1024] @ [Wq|Wk|Wv]
// 256 threads = 8 warps (4 m-warps x 2 n-warps); M-tile 64, N 192, K chunk 32.
// xs stride 36 (==4 mod 32): A-frag LDS banks 4*lr+lc all distinct.
// ws stride 200 (==8 mod 32): B-frag LDS banks 8*lc+lr all distinct.
// Inputs converted to tf32 at stage time (mma requires tf32-format operands).
// ---------------------------------------------------------------------------
#define XS_STRIDE 36
#define WS_STRIDE 200

__global__ __launch_bounds__(256) void qkv_kernel(
    const float* __restrict__ x, const float* __restrict__ Wq,
    const float* __restrict__ Wk, const float* __restrict__ Wv)
{
    __shared__ float xs[64 * XS_STRIDE];   // [row][k]  9216 B
    __shared__ float ws[32 * WS_STRIDE];   // [k][n]   25600 B
    const int tid  = threadIdx.x;
    const int warp = tid >> 5;
    const int lane = tid & 31;
    const int lr   = lane >> 2;      // 0..7
    const int lc   = lane & 3;       // 0..3
    const int mw   = warp >> 1;      // 0..3  m-warp (16 rows each)
    const int nw   = warp & 1;       // 0..1  n-warp (96 cols each)
    const int m0   = blockIdx.x * 64;

    float acc[12][4];
    #pragma unroll
    for (int t = 0; t < 12; t++)
        #pragma unroll
        for (int r = 0; r < 4; r++) acc[t][r] = 0.f;

    for (int k0 = 0; k0 < CC; k0 += 32) {
        __syncthreads();
        // Stage X tile [64][32] (row-major, tf32-rounded)
        #pragma unroll
        for (int l = 0; l < 2; l++) {
            int idx = tid + l * 256;           // 0..511
            int r = idx >> 3, kq = idx & 7;
            float4 v = *(const float4*)&x[(size_t)(m0 + r) * CC + k0 + kq * 4];
            v.x = to_tf32(v.x); v.y = to_tf32(v.y);
            v.z = to_tf32(v.z); v.w = to_tf32(v.w);
            *(float4*)&xs[r * XS_STRIDE + kq * 4] = v;
        }
        // Stage W tile [32][192] (k-major rows, tf32-rounded)
        #pragma unroll
        for (int l = 0; l < 6; l++) {
            int idx = tid + l * 256;           // 0..1535
            int k = idx / 48, f = idx % 48;
            const float* Wm = (f < 16) ? Wq : (f < 32) ? Wk : Wv;
            int c4 = f & 15;
            float4 v = *(const float4*)&Wm[(size_t)(k0 + k) * HH + c4 * 4];
            v.x = to_tf32(v.x); v.y = to_tf32(v.y);
            v.z = to_tf32(v.z); v.w = to_tf32(v.w);
            *(float4*)&ws[k * WS_STRIDE + (f >> 4) * 64 + c4 * 4] = v;
        }
        __syncthreads();

        #pragma unroll
        for (int kk = 0; kk < 4; kk++) {       // 4 k8-steps per chunk
            uint32_t a[4];
            a[0] = __float_as_uint(xs[(mw * 16 + lr    ) * XS_STRIDE + kk * 8 + lc    ]);
            a[1] = __float_as_uint(xs[(mw * 16 + lr + 8) * XS_STRIDE + kk * 8 + lc    ]);
            a[2] = __float_as_uint(xs[(mw * 16 + lr    ) * XS_STRIDE + kk * 8 + lc + 4]);
            a[3] = __float_as_uint(xs[(mw * 16 + lr + 8) * XS_STRIDE + kk * 8 + lc + 4]);
            #pragma unroll
            for (int nt = 0; nt < 12; nt++) {
                // B col-major: B[k][n] = ws[k][n]
                uint32_t b0 = __float_as_uint(
                    ws[(kk * 8 + lc    ) * WS_STRIDE + nw * 96 + nt * 8 + lr]);
                uint32_t b1 = __float_as_uint(
                    ws[(kk * 8 + lc + 4) * WS_STRIDE + nw * 96 + nt * 8 + lr]);
                mma_tf32(acc[nt], a, b0, b1);
            }
        }
    }

    // Epilogue: route to g_K / g_Q / g_V, pre-scale Q by 1024^-0.5, tf32-round.
    #pragma unroll
    for (int nt = 0; nt < 12; nt++) {
        int col = nw * 96 + nt * 8 + lc * 2;          // even; pair never straddles 64
        float* dst = (col < 64) ? g_K : (col < 128) ? g_Q : g_V;
        float sc = (col >= 64 && col < 128) ? 0.03125f : 1.0f;
        int c = col & 63;
        int row0 = m0 + mw * 16 + lr;
        *(float2*)&dst[(size_t)row0 * HH + c] =
            make_float2(to_tf32(acc[nt][0] * sc), to_tf32(acc[nt][1] * sc));
        *(float2*)&dst[(size_t)(row0 + 8) * HH + c] =
            make_float2(to_tf32(acc[nt][2] * sc), to_tf32(acc[nt][3] * sc));
    }
}

// ---------------------------------------------------------------------------
// Flash attention with tf32 mma.sync (m16n8k8), BQ=BK=64, 128 threads.
// 4 warps; warp w owns q-rows [16w,16w+16) -> softmax fully warp-local.
// Work-balanced pair (bx, 63-bx) via two sequential passes: 65 k-tiles/CTA.
// Smem strides: Ks/Ps stride 68 (==4 mod 32), Vs stride 72 (==8 mod 32)
//   -> all mma fragment LDS patterns are bank-conflict-free.
// ---------------------------------------------------------------------------
#define KS_STRIDE 68
#define VS_STRIDE 72
#define PS_STRIDE 68
#define ATTN_SMEM_BYTES ((64*KS_STRIDE + 64*VS_STRIDE + 64*PS_STRIDE) * 4)  // 53248

__global__ __launch_bounds__(128) void attn_kernel(float* __restrict__ out)
{
    extern __shared__ float smem[];
    float* Ks = smem;                         // [64][68]  K tile [key][h]
    float* Vs = smem + 64 * KS_STRIDE;        // [64][72]  V tile [key][h]
    float* Ps = Vs + 64 * VS_STRIDE;          // [64][68]  P tile [q][key]

    const int tid  = threadIdx.x;
    const int warp = tid >> 5;
    const int lane = tid & 31;
    const int lr   = lane >> 2;
    const int lc   = lane & 3;
    const int b    = blockIdx.y;

    for (int pass = 0; pass < 2; pass++) {
        const int qt = pass ? 63 - (int)blockIdx.x : (int)blockIdx.x;
        const int q0 = qt * 64;
        const int qrow_lo = q0 + warp * 16 + lr;
        uint32_t qa[8][4];
        {
            const uint32_t* qb =
                (const uint32_t*)g_Q + ((size_t)b * TT + q0 + warp * 16) * HH;
            #pragma unroll
            for (int ks = 0; ks < 8; ks++) {
                qa[ks][0] = qb[(lr    ) * HH + ks * 8 + lc    ];
                qa[ks][1] = qb[(lr + 8) * HH + ks * 8 + lc    ];
                qa[ks][2] = qb[(lr    ) * HH + ks * 8 + lc + 4];
                qa[ks][3] = qb[(lr + 8) * HH + ks * 8 + lc + 4];
            }
        }

        float O[8][4];
        #pragma unroll
        for (int t = 0; t < 8; t++)
            #pragma unroll
            for (int r = 0; r < 4; r++) O[t][r] = 0.f;
        float m_lo = -1e30f, m_hi = -1e30f, l_lo = 0.f, l_hi = 0.f;

        for (int kt = 0; kt <= qt; kt++) {
            const int k0 = kt * 64;
            __syncthreads();
            {
                const float4* K4 = (const float4*)(g_K + ((size_t)b * TT + k0) * HH);
                const float4* V4 = (const float4*)(g_V + ((size_t)b * TT + k0) * HH);
                #pragma unroll
                for (int l = 0; l < 8; l++) {
                    int idx = tid + l * 128;
                    int r = idx >> 4, c = idx & 15;
                    *(float4*)&Ks[r * KS_STRIDE + c * 4] = K4[r * 16 + c];
                    *(float4*)&Vs[r * VS_STRIDE + c * 4] = V4[r * 16 + c];
                }
            }
            __syncthreads();

            float sD[8][4];
            #pragma unroll
            for (int t = 0; t < 8; t++)
                #pragma unroll
                for (int r = 0; r < 4; r++) sD[t][r] = 0.f;

            #pragma unroll
            for (int nt = 0; nt < 8; nt++) {
                #pragma unroll
                for (int ks = 0; ks < 8; ks++) {
                    uint32_t b0 = __float_as_uint(
                        Ks[(nt * 8 + lr) * KS_STRIDE + ks * 8 + lc]);
                    uint32_t b1 = __float_as_uint(
                        Ks[(nt * 8 + lr) * KS_STRIDE + ks * 8 + lc + 4]);
                    mma_tf32(sD[nt], qa[ks], b0, b1);
                }
            }

            if (kt == qt) {
                #pragma unroll
                for (int nt = 0; nt < 8; nt++) {
                    int key = k0 + nt * 8 + lc * 2;
                    if (key     > qrow_lo    ) sD[nt][0] = -1e30f;
                    if (key + 1 > qrow_lo    ) sD[nt][1] = -1e30f;
                    if (key     > qrow_lo + 8) sD[nt][2] = -1e30f;
                    if (key + 1 > qrow_lo + 8) sD[nt][3] = -1e30f;
                }
            }

            float mt_lo = -1e30f, mt_hi = -1e30f;
            #pragma unroll
            for (int nt = 0; nt < 8; nt++) {
                mt_lo = fmaxf(mt_lo, fmaxf(sD[nt][0], sD[nt][1]));
                mt_hi = fmaxf(mt_hi, fmaxf(sD[nt][2], sD[nt][3]));
            }
            mt_lo = fmaxf(mt_lo, __shfl_xor_sync(0xffffffffu, mt_lo, 1));
            mt_lo = fmaxf(mt_lo, __shfl_xor_sync(0xffffffffu, mt_lo, 2));
            mt_hi = fmaxf(mt_hi, __shfl_xor_sync(0xffffffffu, mt_hi, 1));
            mt_hi = fmaxf(mt_hi, __shfl_xor_sync(0xffffffffu, mt_hi, 2));

            float mn_lo = fmaxf(m_lo, mt_lo);
            float mn_hi = fmaxf(m_hi, mt_hi);
            float alpha_lo = __expf(m_lo - mn_lo);
            float alpha_hi = __expf(m_hi - mn_hi);

            float sum_lo = 0.f, sum_hi = 0.f;
            #pragma unroll
            for (int nt = 0; nt < 8; nt++) {
                sD[nt][0] = __expf(sD[nt][0] - mn_lo); sum_lo += sD[nt][0];
                sD[nt][1] = __expf(sD[nt][1] - mn_lo); sum_lo += sD[nt][1];
                sD[nt][2] = __expf(sD[nt][2] - mn_hi); sum_hi += sD[nt][2];
                sD[nt][3] = __expf(sD[nt][3] - mn_hi); sum_hi += sD[nt][3];
            }
            sum_lo += __shfl_xor_sync(0xffffffffu, sum_lo, 1);
            sum_lo += __shfl_xor_sync(0xffffffffu, sum_lo, 2);
            sum_hi += __shfl_xor_sync(0xffffffffu, sum_hi, 1);
            sum_hi += __shfl_xor_sync(0xffffffffu, sum_hi, 2);
            l_lo = l_lo * alpha_lo + sum_lo;  m_lo = mn_lo;
            l_hi = l_hi * alpha_hi + sum_hi;  m_hi = mn_hi;

            #pragma unroll
            for (int t = 0; t < 8; t++) {
                O[t][0] *= alpha_lo; O[t][1] *= alpha_lo;
                O[t][2] *= alpha_hi; O[t][3] *= alpha_hi;
            }

            #pragma unroll
            for (int nt = 0; nt < 8; nt++) {
                float2* d0 = (float2*)&Ps[(warp * 16 + lr) * PS_STRIDE + nt * 8 + lc * 2];
                float2* d1 = (float2*)&Ps[(warp * 16 + lr + 8) * PS_STRIDE + nt * 8 + lc * 2];
                *d0 = make_float2(to_tf32(sD[nt][0]), to_tf32(sD[nt][1]));
                *d1 = make_float2(to_tf32(sD[nt][2]), to_tf32(sD[nt][3]));
            }
            __syncwarp();

            #pragma unroll
            for (int ks = 0; ks < 8; ks++) {
                uint32_t pa[4];
                pa[0] = __float_as_uint(Ps[(warp * 16 + lr    ) * PS_STRIDE + ks * 8 + lc    ]);
                pa[1] = __float_as_uint(Ps[(warp * 16 + lr + 8) * PS_STRIDE + ks * 8 + lc    ]);
                pa[2] = __float_as_uint(Ps[(warp * 16 + lr    ) * PS_STRIDE + ks * 8 + lc + 4]);
                pa[3] = __float_as_uint(Ps[(warp * 16 + lr + 8) * PS_STRIDE + ks * 8 + lc + 4]);
                #pragma unroll
                for (int ht = 0; ht < 8; ht++) {
                    uint32_t b0 = __float_as_uint(
                        Vs[(ks * 8 + lc    ) * VS_STRIDE + ht * 8 + lr]);
                    uint32_t b1 = __float_as_uint(
                        Vs[(ks * 8 + lc + 4) * VS_STRIDE + ht * 8 + lr]);
                    mma_tf32(O[ht], pa, b0, b1);
                }
            }
        }

        float il_lo = 1.f / l_lo, il_hi = 1.f / l_hi;
        #pragma unroll
        for (int ht = 0; ht < 8; ht++) {
            int col = ht * 8 + lc * 2;
            *(float2*)&out[((size_t)b * TT + qrow_lo    ) * HH + col] =
                make_float2(O[ht][0] * il_lo, O[ht][1] * il_lo);
            *(float2*)&out[((size_t)b * TT + qrow_lo + 8) * HH + col] =
                make_float2(O[ht][2] * il_hi, O[ht][3] * il_hi);
        }
    }
}

extern "C" void kernel_launch(void* const* d_in, const int* in_sizes, int n_in,
                              void* d_out, int out_size) {
    const float* x  = (const float*)d_in[0];
    const float* Wq = (const float*)d_in[1];
    const float* Wk = (const float*)d_in[2];
    const float* Wv = (const float*)d_in[3];
    float* out = (float*)d_out;

    cudaFuncSetAttribute(attn_kernel,
                         cudaFuncAttributeMaxDynamicSharedMemorySize,
                         ATTN_SMEM_BYTES);

    qkv_kernel<<<NROWS / 64, 256>>>(x, Wq, Wk, Wv);
    attn_kernel<<<dim3(32, BB), 128, ATTN_SMEM_BYTES>>>(out);
}